// round 9
// baseline (speedup 1.0000x reference)
#include <cuda_runtime.h>
#include <cuda_fp16.h>
#include <cstdint>

#define DIM 4096
#define BM 128
#define BN 128
#define BK 64
#define KT (DIM / BK)            // 64 k-stages
#define NSTAGE 6                 // 6-deep ring -> 192KB, forces occ 1
#define STAGE_BYTES 32768        // A 128x128B (16KB) + B 128x128B (16KB)
#define SMEM_SCALE (NSTAGE * STAGE_BYTES)          // 196608
#define SMEM_BIAS  (SMEM_SCALE + BN * 4)
#define SMEM_BYTES (SMEM_BIAS + BN * 4)            // 197632
#define NTHREADS 512

// fp16 scratch operands (allocation-free: __device__ globals)
__device__ __half g_xh[(size_t)DIM * DIM];
__device__ __half g_wh[(size_t)DIM * DIM];

// ---------------------------------------------------------------------------
// Fused pre-pass: blocks [0, 16384) convert x fp32->fp16,
//                 blocks [16384, 24576) dequant w int4 nibbles -> fp16 (exact)
// ---------------------------------------------------------------------------
__device__ __forceinline__ __half2 deq_nib(int v) {
    return __halves2half2(__int2half_rn((v & 0xF) - 8),
                          __int2half_rn(((v >> 4) & 0xF) - 8));
}

__global__ void __launch_bounds__(256) prep_kernel(const float4* __restrict__ x,
                                                   const int4* __restrict__ wp) {
    int b = blockIdx.x;
    if (b < 16384) {
        int i = b * 256 + threadIdx.x;
        float4 v = x[i];
        union { __half2 h[2]; uint2 u; } p;
        p.h[0] = __floats2half2_rn(v.x, v.y);
        p.h[1] = __floats2half2_rn(v.z, v.w);
        ((uint2*)g_xh)[i] = p.u;
    } else {
        int i = (b - 16384) * 256 + threadIdx.x;
        int4 v = wp[i];
        union { __half2 h[4]; uint4 u; } p;
        p.h[0] = deq_nib(v.x); p.h[1] = deq_nib(v.y);
        p.h[2] = deq_nib(v.z); p.h[3] = deq_nib(v.w);
        ((uint4*)g_wh)[i] = p.u;
    }
}

// ---------------------------------------------------------------------------
// Baseline-ISA helpers (ptxas target is plain sm_103: no tcgen05/TMA)
// ---------------------------------------------------------------------------
__device__ __forceinline__ uint32_t smem_u32(const void* p) {
    uint32_t a;
    asm("{ .reg .u64 t; cvta.to.shared.u64 t, %1; cvt.u32.u64 %0, t; }" : "=r"(a) : "l"(p));
    return a;
}

#define CP_ASYNC16(sm, gp) \
    asm volatile("cp.async.cg.shared.global [%0], [%1], 16;" :: "r"(sm), "l"(gp) : "memory")
#define CP_COMMIT() asm volatile("cp.async.commit_group;" ::: "memory")
#define CP_WAIT(n)  asm volatile("cp.async.wait_group %0;" :: "n"(n) : "memory")

#define LDSM_X4(r0, r1, r2, r3, addr) \
    asm volatile("ldmatrix.sync.aligned.m8n8.x4.shared.b16 {%0,%1,%2,%3}, [%4];" \
                 : "=r"(r0), "=r"(r1), "=r"(r2), "=r"(r3) : "r"(addr))

#define MMA16816(c, a, b) \
    asm volatile("mma.sync.aligned.m16n8k16.row.col.f32.f16.f16.f32 " \
                 "{%0,%1,%2,%3}, {%4,%5,%6,%7}, {%8,%9}, {%0,%1,%2,%3};" \
                 : "+f"((c)[0]), "+f"((c)[1]), "+f"((c)[2]), "+f"((c)[3]) \
                 : "r"((a)[0]), "r"((a)[1]), "r"((a)[2]), "r"((a)[3]), \
                   "r"((b)[0]), "r"((b)[1]))

// ---------------------------------------------------------------------------
// GEMM: out[N, OUT] = x_h[N, K] @ w_h[OUT, K]^T, epilogue: *scale[o] + bias[o]
// CTA 128x128, 512 threads: 16 warps in a 4x4 grid of 32x32 warp tiles.
// 6-stage SMEM ring (192KB -> occ 1), ONE barrier per 2 k-stages, batch
// prefetch at barriers, register double-buffered fragments, XOR addressing.
// Grid 1024 / 148 SMs = 6.92 waves -> ~1% tail.
// ---------------------------------------------------------------------------
__global__ void __launch_bounds__(NTHREADS, 1)
gemm_kernel(const float* __restrict__ ws, const float* __restrict__ bs,
            float* __restrict__ out) {
    extern __shared__ char smem[];
    const uint32_t sb = smem_u32(smem);
    const int tid = threadIdx.x, wid = tid >> 5, lane = tid & 31;
    const int wr = wid >> 2, wc = wid & 3;             // warp grid 4(m) x 4(n)
    const int m0 = blockIdx.y * BM, n0 = blockIdx.x * BN;

    // scale/bias for this CTA's 128 output columns (visible after 1st barrier)
    if (tid < BN)            ((float*)(smem + SMEM_SCALE))[tid]      = ws[n0 + tid];
    else if (tid < 2 * BN)   ((float*)(smem + SMEM_BIAS))[tid - BN]  = bs[n0 + tid - BN];

    // ---- cp.async geometry: per thread 2 A chunks + 2 B chunks (16B each) ----
    const int ldRow = tid >> 3;                        // 0..63 (also +64)
    const int ldCol = tid & 7;                         // 16B chunk within 128B row
    const int scol  = ldCol ^ (ldRow & 7);             // xor-swizzle (8x16B); (row+64)&7 same
    const __half* gA = g_xh + (size_t)(m0 + ldRow) * DIM + ldCol * 8;
    const __half* gB = g_wh + (size_t)(n0 + ldRow) * DIM + ldCol * 8;
    const uint32_t sA = sb + ldRow * 128 + scol * 16;
    const uint32_t sB = sA + 16384;

#define LOAD_STAGE(k)                                                        \
    {                                                                        \
        uint32_t so = ((k) % NSTAGE) * STAGE_BYTES;                          \
        const __half* ga = gA + (size_t)(k) * BK;                            \
        const __half* gb = gB + (size_t)(k) * BK;                            \
        CP_ASYNC16(sA + so,        ga);                                      \
        CP_ASYNC16(sA + so + 8192, ga + (size_t)64 * DIM);                   \
        CP_ASYNC16(sB + so,        gb);                                      \
        CP_ASYNC16(sB + so + 8192, gb + (size_t)64 * DIM);                   \
    }

    // ---- ldmatrix fragment addresses (XOR trick: addr(ks) = base ^ (ks<<5)) ----
    const int aRow  = wr * 32 + (lane & 15);
    const int bRow  = wc * 32 + (lane & 15);
    const int kHalf = lane >> 4;
    uint32_t offA[2], offB[2];
#pragma unroll
    for (int mi = 0; mi < 2; mi++)
        offA[mi] = (uint32_t)((aRow + mi * 16) * 128 + ((kHalf ^ (aRow & 7)) << 4));
#pragma unroll
    for (int p = 0; p < 2; p++)
        offB[p] = (uint32_t)(16384 + (bRow + p * 16) * 128 + ((kHalf ^ (bRow & 7)) << 4));

    float c[2][4][4];
#pragma unroll
    for (int mi = 0; mi < 2; mi++)
#pragma unroll
        for (int ni = 0; ni < 4; ni++)
#pragma unroll
            for (int e = 0; e < 4; e++) c[mi][ni][e] = 0.0f;

    uint32_t a[2][2][4], b[2][4][2];

#define LOAD_FRAGS(st, ks, buf)                                              \
    {                                                                        \
        _Pragma("unroll")                                                    \
        for (int mi = 0; mi < 2; mi++)                                       \
            LDSM_X4(a[buf][mi][0], a[buf][mi][1], a[buf][mi][2],             \
                    a[buf][mi][3], ((st) + offA[mi]) ^ ((ks) << 5));         \
        _Pragma("unroll")                                                    \
        for (int p = 0; p < 2; p++)                                          \
            LDSM_X4(b[buf][2 * p][0], b[buf][2 * p + 1][0],                  \
                    b[buf][2 * p][1], b[buf][2 * p + 1][1],                  \
                    ((st) + offB[p]) ^ ((ks) << 5));                         \
    }

#define MMA_ALL(buf)                                                         \
    {                                                                        \
        _Pragma("unroll")                                                    \
        for (int mi = 0; mi < 2; mi++)                                       \
            _Pragma("unroll")                                                \
            for (int ni = 0; ni < 4; ni++)                                   \
                MMA16816(c[mi][ni], a[buf][mi], b[buf][ni]);                 \
    }

    // prologue: 2 batches of 2 stages
    LOAD_STAGE(0); LOAD_STAGE(1); CP_COMMIT();
    LOAD_STAGE(2); LOAD_STAGE(3); CP_COMMIT();

#pragma unroll 1
    for (int bt = 0; bt < KT / 2; bt++) {
        CP_WAIT(1);                 // batch bt (stages 2bt, 2bt+1) resident
        __syncthreads();            // all warps finished stages <= 2bt-1 ->
                                    // slots (2bt+4)%6, (2bt+5)%6 (stages 2bt-2, 2bt-1) reusable

        if (bt + 2 < KT / 2) {      // batch prefetch, 2 stages ahead in the ring
            LOAD_STAGE(2 * bt + 4);
            LOAD_STAGE(2 * bt + 5);
            CP_COMMIT();
        }

#pragma unroll
        for (int s = 0; s < 2; s++) {
            const int k = 2 * bt + s;
            const uint32_t st = sb + (k % NSTAGE) * STAGE_BYTES;
            LOAD_FRAGS(st, 0, 0);
#pragma unroll
            for (int ks = 0; ks < 4; ks++) {
                if (ks < 3) LOAD_FRAGS(st, ks + 1, (ks + 1) & 1);
                MMA_ALL(ks & 1);
            }
        }
    }

    // ---- epilogue: scale * acc + bias, fp32 paired stores ----
    const float* ssc = (const float*)(smem + SMEM_SCALE);
    const float* sbi = (const float*)(smem + SMEM_BIAS);
    const int rBase = m0 + wr * 32 + (lane >> 2);
    const int cBase = wc * 32 + (lane & 3) * 2;
#pragma unroll
    for (int mi = 0; mi < 2; mi++) {
#pragma unroll
        for (int ni = 0; ni < 4; ni++) {
            const int col = cBase + ni * 8;
            const float s0 = ssc[col], s1 = ssc[col + 1];
            const float b0 = sbi[col], b1 = sbi[col + 1];
            float* p0 = out + (size_t)(rBase + mi * 16) * DIM + n0 + col;
            float* p1 = p0 + (size_t)8 * DIM;
            *(float2*)p0 = make_float2(c[mi][ni][0] * s0 + b0, c[mi][ni][1] * s1 + b1);
            *(float2*)p1 = make_float2(c[mi][ni][2] * s0 + b0, c[mi][ni][3] * s1 + b1);
        }
    }
}

// ---------------------------------------------------------------------------
// Launch
// ---------------------------------------------------------------------------
extern "C" void kernel_launch(void* const* d_in, const int* in_sizes, int n_in,
                              void* d_out, int out_size) {
    (void)in_sizes; (void)n_in; (void)out_size;
    const float* x    = (const float*)d_in[0];
    const int*   wp   = (const int*)d_in[1];
    const float* ws   = (const float*)d_in[2];
    const float* bias = (const float*)d_in[3];
    float* out = (float*)d_out;

    cudaFuncSetAttribute(gemm_kernel, cudaFuncAttributeMaxDynamicSharedMemorySize, SMEM_BYTES);

    prep_kernel<<<16384 + 8192, 256>>>((const float4*)x, (const int4*)wp);
    gemm_kernel<<<dim3(DIM / BN, DIM / BM), NTHREADS, SMEM_BYTES>>>(ws, bias, out);
}

// round 12
// speedup vs baseline: 1.3237x; 1.3237x over previous
#include <cuda_runtime.h>
#include <cuda_fp16.h>
#include <cstdint>

#define DIM 4096
#define BM 128
#define BN 128
#define BK 64
#define KT (DIM / BK)            // 64 k-stages
#define NSTAGE 3
#define STAGE_BYTES 32768        // A 128x128B (16KB) + B 128x128B (16KB)
#define SMEM_SCALE (NSTAGE * STAGE_BYTES)
#define SMEM_BIAS  (SMEM_SCALE + BN * 4)
#define SMEM_BYTES (SMEM_BIAS + BN * 4)   // 99328 -> occ 2 per SM
#define NTHREADS 128

// fp16 scratch operands (allocation-free: __device__ globals)
__device__ __half g_xh[(size_t)DIM * DIM];
__device__ __half g_wh[(size_t)DIM * DIM];

// ---------------------------------------------------------------------------
// Fused pre-pass: blocks [0, 16384) convert x fp32->fp16,
//                 blocks [16384, 24576) dequant w int4 nibbles -> fp16 (exact)
// ---------------------------------------------------------------------------
__device__ __forceinline__ __half2 deq_nib(int v) {
    return __halves2half2(__int2half_rn((v & 0xF) - 8),
                          __int2half_rn(((v >> 4) & 0xF) - 8));
}

__global__ void __launch_bounds__(256) prep_kernel(const float4* __restrict__ x,
                                                   const int4* __restrict__ wp) {
    int b = blockIdx.x;
    if (b < 16384) {
        int i = b * 256 + threadIdx.x;
        float4 v = x[i];
        union { __half2 h[2]; uint2 u; } p;
        p.h[0] = __floats2half2_rn(v.x, v.y);
        p.h[1] = __floats2half2_rn(v.z, v.w);
        ((uint2*)g_xh)[i] = p.u;
    } else {
        int i = (b - 16384) * 256 + threadIdx.x;
        int4 v = wp[i];
        union { __half2 h[4]; uint4 u; } p;
        p.h[0] = deq_nib(v.x); p.h[1] = deq_nib(v.y);
        p.h[2] = deq_nib(v.z); p.h[3] = deq_nib(v.w);
        ((uint4*)g_wh)[i] = p.u;
    }
}

// ---------------------------------------------------------------------------
// Baseline-ISA helpers (ptxas target is plain sm_103: no tcgen05/TMA)
// ---------------------------------------------------------------------------
__device__ __forceinline__ uint32_t smem_u32(const void* p) {
    uint32_t a;
    asm("{ .reg .u64 t; cvta.to.shared.u64 t, %1; cvt.u32.u64 %0, t; }" : "=r"(a) : "l"(p));
    return a;
}

#define CP_ASYNC16(sm, gp) \
    asm volatile("cp.async.cg.shared.global [%0], [%1], 16;" :: "r"(sm), "l"(gp) : "memory")
#define CP_COMMIT() asm volatile("cp.async.commit_group;" ::: "memory")
#define CP_WAIT(n)  asm volatile("cp.async.wait_group %0;" :: "n"(n) : "memory")

#define LDSM_X4(r0, r1, r2, r3, addr) \
    asm volatile("ldmatrix.sync.aligned.m8n8.x4.shared.b16 {%0,%1,%2,%3}, [%4];" \
                 : "=r"(r0), "=r"(r1), "=r"(r2), "=r"(r3) : "r"(addr))

#define MMA16816(c, a, b) \
    asm volatile("mma.sync.aligned.m16n8k16.row.col.f32.f16.f16.f32 " \
                 "{%0,%1,%2,%3}, {%4,%5,%6,%7}, {%8,%9}, {%0,%1,%2,%3};" \
                 : "+f"((c)[0]), "+f"((c)[1]), "+f"((c)[2]), "+f"((c)[3]) \
                 : "r"((a)[0]), "r"((a)[1]), "r"((a)[2]), "r"((a)[3]), \
                   "r"((b)[0]), "r"((b)[1]))

// ---------------------------------------------------------------------------
// GEMM: out[N, OUT] = x_h[N, K] @ w_h[OUT, K]^T, epilogue: *scale[o] + bias[o]
// CTA 128x128, 128 threads (4 warps, 2x2 of 64x64 tiles), 3-stage ring, occ 2.
// MID-ITERATION barrier: CP_WAIT(1) + __syncthreads sit after the last
// shared-read of stage k (chunk-3 LDSM), then stage k+1's chunk-0 fragments
// are prefetched (race-free: wait+barrier ordered before the read), then
// stage k+3 is issued into the just-freed slot, and chunk-3's 32 MMAs
// execute right after the barrier so the tensor pipe never drains.
// ---------------------------------------------------------------------------
__global__ void __launch_bounds__(NTHREADS, 2)
gemm_kernel(const float* __restrict__ ws, const float* __restrict__ bs,
            float* __restrict__ out) {
    extern __shared__ char smem[];
    const uint32_t sb = smem_u32(smem);
    const int tid = threadIdx.x, wid = tid >> 5, lane = tid & 31;
    const int wr = wid >> 1, wc = wid & 1;             // warp grid 2(m) x 2(n)
    const int m0 = blockIdx.y * BM, n0 = blockIdx.x * BN;

    // scale/bias for this CTA's 128 output columns
    ((float*)(smem + SMEM_SCALE))[tid] = ws[n0 + tid];
    ((float*)(smem + SMEM_BIAS))[tid]  = bs[n0 + tid];

    // ---- cp.async geometry: per thread 8 A chunks + 8 B chunks (16B each) ----
    const int ldRow = tid >> 3;                        // 0..15
    const int ldCol = tid & 7;                         // 16B chunk within 128B row
    const int scol  = ldCol ^ (ldRow & 7);             // xor-swizzle (8x16B)
    const __half* gA = g_xh + (size_t)(m0 + ldRow) * DIM + ldCol * 8;
    const __half* gB = g_wh + (size_t)(n0 + ldRow) * DIM + ldCol * 8;
    const uint32_t sA = sb + ldRow * 128 + scol * 16;
    const uint32_t sB = sA + 16384;

#define LOAD_STAGE(k)                                                        \
    if ((k) < KT) {                                                          \
        uint32_t so = ((k) % NSTAGE) * STAGE_BYTES;                          \
        const __half* ga = gA + (size_t)(k) * BK;                            \
        const __half* gb = gB + (size_t)(k) * BK;                            \
        _Pragma("unroll")                                                    \
        for (int i = 0; i < 8; i++) {                                        \
            CP_ASYNC16(sA + so + i * 2048, ga + (size_t)i * 16 * DIM);       \
            CP_ASYNC16(sB + so + i * 2048, gb + (size_t)i * 16 * DIM);       \
        }                                                                    \
    }

    // ---- ldmatrix fragment addresses (XOR trick: addr(ks) = base ^ (ks<<5)) ----
    const int aRow  = wr * 64 + (lane & 15);
    const int bRow  = wc * 64 + (lane & 15);
    const int kHalf = lane >> 4;
    uint32_t offA[4], offB[4];
#pragma unroll
    for (int mi = 0; mi < 4; mi++)
        offA[mi] = (uint32_t)((aRow + mi * 16) * 128 + ((kHalf ^ (aRow & 7)) << 4));
#pragma unroll
    for (int p = 0; p < 4; p++)
        offB[p] = (uint32_t)(16384 + (bRow + p * 16) * 128 + ((kHalf ^ (bRow & 7)) << 4));

    float c[4][8][4];
#pragma unroll
    for (int mi = 0; mi < 4; mi++)
#pragma unroll
        for (int ni = 0; ni < 8; ni++)
#pragma unroll
            for (int e = 0; e < 4; e++) c[mi][ni][e] = 0.0f;

    uint32_t a[2][4][4], b[2][8][2];

#define LOAD_FRAGS(st, ks, buf)                                              \
    {                                                                        \
        _Pragma("unroll")                                                    \
        for (int mi = 0; mi < 4; mi++)                                       \
            LDSM_X4(a[buf][mi][0], a[buf][mi][1], a[buf][mi][2],             \
                    a[buf][mi][3], ((st) + offA[mi]) ^ ((ks) << 5));         \
        _Pragma("unroll")                                                    \
        for (int p = 0; p < 4; p++)                                          \
            LDSM_X4(b[buf][2 * p][0], b[buf][2 * p + 1][0],                  \
                    b[buf][2 * p][1], b[buf][2 * p + 1][1],                  \
                    ((st) + offB[p]) ^ ((ks) << 5));                         \
    }

#define MMA_ALL(buf)                                                         \
    {                                                                        \
        _Pragma("unroll")                                                    \
        for (int mi = 0; mi < 4; mi++)                                       \
            _Pragma("unroll")                                                \
            for (int ni = 0; ni < 8; ni++)                                   \
                MMA16816(c[mi][ni], a[buf][mi], b[buf][ni]);                 \
    }

    // ---- prologue: 3 stages in flight; stage-0 chunk-0 fragments in b0 ----
    LOAD_STAGE(0); CP_COMMIT();
    LOAD_STAGE(1); CP_COMMIT();
    LOAD_STAGE(2); CP_COMMIT();
    CP_WAIT(2);                      // stage 0 resident (this thread)
    __syncthreads();                 // stage 0 + scale/bias visible CTA-wide
    LOAD_FRAGS(sb, 0, 0);

#pragma unroll 1
    for (int k = 0; k < KT; k++) {
        const uint32_t st  = sb + (k % NSTAGE) * STAGE_BYTES;
        const uint32_t stn = sb + ((k + 1) % NSTAGE) * STAGE_BYTES;

        LOAD_FRAGS(st, 1, 1);  MMA_ALL(0);      // chunk 0
        LOAD_FRAGS(st, 2, 0);  MMA_ALL(1);      // chunk 1
        LOAD_FRAGS(st, 3, 1);  MMA_ALL(0);      // chunk 2 (last LDS read of stage k)

        if (k + 1 < KT) {
            CP_WAIT(1);              // stage k+1 copies done (this thread)
            __syncthreads();         // ... and visible CTA-wide; also: all
                                     // threads finished reading stage k
            LOAD_FRAGS(stn, 0, 0);   // race-free prefetch of next chunk 0
            LOAD_STAGE(k + 3);       // into slot k%3 (reads done, barrier'd)
            CP_COMMIT();
        }
        MMA_ALL(1);                  // chunk 3: 32 MMAs cover the prefetch
    }

    // ---- epilogue: scale * acc + bias, fp32 paired stores ----
    const float* ssc = (const float*)(smem + SMEM_SCALE);
    const float* sbi = (const float*)(smem + SMEM_BIAS);
    const int rBase = m0 + wr * 64 + (lane >> 2);
    const int cBase = wc * 64 + (lane & 3) * 2;
#pragma unroll
    for (int mi = 0; mi < 4; mi++) {
#pragma unroll
        for (int ni = 0; ni < 8; ni++) {
            const int col = cBase + ni * 8;
            const float s0 = ssc[col], s1 = ssc[col + 1];
            const float b0 = sbi[col], b1 = sbi[col + 1];
            float* p0 = out + (size_t)(rBase + mi * 16) * DIM + n0 + col;
            float* p1 = p0 + (size_t)8 * DIM;
            *(float2*)p0 = make_float2(c[mi][ni][0] * s0 + b0, c[mi][ni][1] * s1 + b1);
            *(float2*)p1 = make_float2(c[mi][ni][2] * s0 + b0, c[mi][ni][3] * s1 + b1);
        }
    }
}

// ---------------------------------------------------------------------------
// Launch
// ---------------------------------------------------------------------------
extern "C" void kernel_launch(void* const* d_in, const int* in_sizes, int n_in,
                              void* d_out, int out_size) {
    (void)in_sizes; (void)n_in; (void)out_size;
    const float* x    = (const float*)d_in[0];
    const int*   wp   = (const int*)d_in[1];
    const float* ws   = (const float*)d_in[2];
    const float* bias = (const float*)d_in[3];
    float* out = (float*)d_out;

    cudaFuncSetAttribute(gemm_kernel, cudaFuncAttributeMaxDynamicSharedMemorySize, SMEM_BYTES);

    prep_kernel<<<16384 + 8192, 256>>>((const float4*)x, (const int4*)wp);
    gemm_kernel<<<dim3(DIM / BN, DIM / BM), NTHREADS, SMEM_BYTES>>>(ws, bias, out);
}